// round 12
// baseline (speedup 1.0000x reference)
#include <cuda_runtime.h>
#include <math.h>
#include <stdint.h>

#define Bb 256
#define Nn 1000
#define Dd 512
#define NEGINF (-INFINITY)
#define NORM_MHA 0.125f
#define NORM_PTR 0.04419417382415922f

static __device__ float g_state[Bb * Dd];
static __device__ float g_Qf[Bb * Dd];
static __device__ float g_Qt[Bb * 8 * Dd];
static __device__ float g_ys2[2 * Bb * 8 * Dd];
static __device__ float g_m2[2 * Bb * 8];
static __device__ float g_l2[2 * Bb * 8];
static __device__ float g_mhaH[Bb * Dd];
static __device__ float g_mo[Bb * Dd];
static __device__ float g_z[Bb * Dd];
static __device__ float g_tv[Bb * Nn];

// ---------- f32x2 helpers ----------
__device__ __forceinline__ unsigned long long pack2(float a, float b) {
    unsigned long long r;
    asm("mov.b64 %0,{%1,%2};" : "=l"(r) : "f"(a), "f"(b));
    return r;
}
__device__ __forceinline__ void unpack2(unsigned long long v, float& a, float& b) {
    asm("mov.b64 {%0,%1},%2;" : "=f"(a), "=f"(b) : "l"(v));
}
__device__ __forceinline__ void ffma2(unsigned long long& d, unsigned long long a, unsigned long long b) {
    asm("fma.rn.f32x2 %0,%1,%2,%0;" : "+l"(d) : "l"(a), "l"(b));
}
__device__ __forceinline__ void fmul2(unsigned long long& d, unsigned long long a) {
    asm("mul.rn.f32x2 %0,%0,%1;" : "+l"(d) : "l"(a));
}

// ---------- mbarrier + bulk-copy helpers ----------
__device__ __forceinline__ uint32_t smem_u32(const void* p) {
    return (uint32_t)__cvta_generic_to_shared(p);
}
__device__ __forceinline__ void mbar_init(uint32_t a, uint32_t c) {
    asm volatile("mbarrier.init.shared.b64 [%0],%1;" ::"r"(a), "r"(c) : "memory");
}
__device__ __forceinline__ void mbar_expect(uint32_t a, uint32_t bytes) {
    asm volatile("mbarrier.arrive.expect_tx.shared.b64 _,[%0],%1;" ::"r"(a), "r"(bytes) : "memory");
}
__device__ __forceinline__ void mbar_wait(uint32_t a, uint32_t phase) {
    asm volatile(
        "{\n\t.reg .pred P;\n\t"
        "WL%=:\n\t"
        "mbarrier.try_wait.parity.acquire.cta.shared::cta.b64 P,[%0],%1,0x989680;\n\t"
        "@P bra WD%=;\n\t"
        "bra WL%=;\n\t"
        "WD%=:\n\t}"
        ::"r"(a), "r"(phase) : "memory");
}
__device__ __forceinline__ void bulkcp(uint32_t dsh, const void* g, uint32_t n, uint32_t mb) {
    asm volatile("cp.async.bulk.shared::cta.global.mbarrier::complete_tx::bytes [%0],[%1],%2,[%3];"
                 ::"r"(dsh), "l"(g), "r"(n), "r"(mb) : "memory");
}

__device__ __forceinline__ void fill8(const float* __restrict__ Xh, const int* __restrict__ smk,
                                      uint32_t dsh, uint32_t mb, int t, int lane) {
    int ntok = (t == 62) ? 4 : 8;
    int tok = t * 8 + lane;
    bool act = (lane < ntok) && (smk[tok] == 0);
    unsigned bal = __ballot_sync(0xffffffffu, act);
    int cnt = __popc(bal);
    if (cnt == 0) {
        if (lane == 0) {
            mbar_expect(mb, 2048);
            bulkcp(dsh, Xh + (size_t)t * 8 * 512, 2048, mb);
        }
    } else {
        if (lane == 0) mbar_expect(mb, (uint32_t)cnt * 2048);
        __syncwarp();
        if (act) bulkcp(dsh + lane * 2048, Xh + (size_t)tok * 512, 2048, mb);
    }
}

// =============== kS: state = [x0,dc]@W_fc + pool@W_fc1 ; grid(4,32) x 128, f32x2
__global__ void __launch_bounds__(128) kS(const float* __restrict__ X, const float* __restrict__ pool,
                                          const float* __restrict__ dc, const float* __restrict__ Wfc,
                                          const float* __restrict__ Wfc1) {
    __shared__ float sx[512 * 8], sp[512 * 8], sdc[8];
    int j0 = blockIdx.x * 128, b0 = blockIdx.y * 8, tid = threadIdx.x;
    for (int i = tid; i < 4096; i += 128) {
        int bb = i >> 9, e = i & 511;
        sx[e * 8 + bb] = X[(size_t)(b0 + bb) * (Nn * Dd) + e];
        sp[e * 8 + bb] = pool[(b0 + bb) * Dd + e];
    }
    if (tid < 8) sdc[tid] = dc[b0 + tid];
    __syncthreads();
    int j = j0 + tid;
    unsigned long long acc[4] = {0ULL, 0ULL, 0ULL, 0ULL};
    for (int e = 0; e < 512; e++) {
        float w0 = Wfc[e * Dd + j], w1 = Wfc1[e * Dd + j];
        unsigned long long w00 = pack2(w0, w0), w11 = pack2(w1, w1);
        ulonglong2 a0 = *(const ulonglong2*)(sx + e * 8);
        ulonglong2 a1 = *(const ulonglong2*)(sx + e * 8 + 4);
        ulonglong2 c0 = *(const ulonglong2*)(sp + e * 8);
        ulonglong2 c1 = *(const ulonglong2*)(sp + e * 8 + 4);
        ffma2(acc[0], a0.x, w00); ffma2(acc[0], c0.x, w11);
        ffma2(acc[1], a0.y, w00); ffma2(acc[1], c0.y, w11);
        ffma2(acc[2], a1.x, w00); ffma2(acc[2], c1.x, w11);
        ffma2(acc[3], a1.y, w00); ffma2(acc[3], c1.y, w11);
    }
    float wl = Wfc[512 * Dd + j];
#pragma unroll
    for (int p = 0; p < 4; p++) {
        float a, b;
        unpack2(acc[p], a, b);
        g_state[(b0 + 2 * p) * Dd + j] = a + sdc[2 * p] * wl;
        g_state[(b0 + 2 * p + 1) * Dd + j] = b + sdc[2 * p + 1] * wl;
    }
}

// =============== kMM: Out = A@W ; 8 batches/CTA ; grid(4,32) x 128, f32x2
__global__ void __launch_bounds__(128) kMM(const float* __restrict__ W, int mode) {
    __shared__ float sa[512 * 8];
    const float* A = mode ? g_mhaH : g_state;
    float* Out = mode ? g_mo : g_Qf;
    int j0 = blockIdx.x * 128, b0 = blockIdx.y * 8, tid = threadIdx.x;
    for (int i = tid; i < 4096; i += 128) sa[(i & 511) * 8 + (i >> 9)] = A[(b0 + (i >> 9)) * Dd + (i & 511)];
    __syncthreads();
    int j = j0 + tid;
    unsigned long long acc[4] = {0ULL, 0ULL, 0ULL, 0ULL};
    for (int f = 0; f < 512; f++) {
        float wv = W[f * Dd + j];
        unsigned long long ww = pack2(wv, wv);
        ulonglong2 a0 = *(const ulonglong2*)(sa + f * 8);
        ulonglong2 a1 = *(const ulonglong2*)(sa + f * 8 + 4);
        ffma2(acc[0], a0.x, ww); ffma2(acc[1], a0.y, ww);
        ffma2(acc[2], a1.x, ww); ffma2(acc[3], a1.y, ww);
    }
#pragma unroll
    for (int p = 0; p < 4; p++) {
        float a, b;
        unpack2(acc[p], a, b);
        Out[(b0 + 2 * p) * Dd + j] = a;
        Out[(b0 + 2 * p + 1) * Dd + j] = b;
    }
}

// =============== kQt: Qt[b][h][e] ; 8 batches/CTA ; grid(4,32) x 128, f32x2 over d
__global__ void __launch_bounds__(128) kQt(const float* __restrict__ Wk) {
    __shared__ float sq[8 * 512];
    int e0 = blockIdx.x * 128, b0 = blockIdx.y * 8, tid = threadIdx.x;
    for (int i = tid; i < 4096; i += 128) sq[i] = g_Qf[(b0 + (i >> 9)) * Dd + (i & 511)];
    __syncthreads();
    int e = e0 + tid;
    const float* wrow = Wk + (size_t)e * Dd;
    for (int h = 0; h < 8; h++) {
        unsigned long long accp[8];
#pragma unroll
        for (int k = 0; k < 8; k++) accp[k] = 0ULL;
        const float* wr = wrow + h * 64;
#pragma unroll
        for (int d4 = 0; d4 < 16; d4++) {
            float4 wv = *(const float4*)(wr + d4 * 4);
            unsigned long long w01 = pack2(wv.x, wv.y), w23 = pack2(wv.z, wv.w);
#pragma unroll
            for (int bb = 0; bb < 8; bb++) {
                ulonglong2 q2 = *(const ulonglong2*)(sq + bb * 512 + h * 64 + d4 * 4);
                ffma2(accp[bb], w01, q2.x);
                ffma2(accp[bb], w23, q2.y);
            }
        }
#pragma unroll
        for (int bb = 0; bb < 8; bb++) {
            float a, b;
            unpack2(accp[bb], a, b);
            g_Qt[(size_t)(b0 + bb) * 4096 + h * 512 + e] = (a + b) * NORM_MHA;
        }
    }
}

// =============== kB: pass 1, half-batch CTAs (grid (2,256) x 256) ===============
// floats: xs[3*4096] | cpart[256] | pbuf2[256] | s_m[8] s_l[8] s_scale[16] s_any[2] s_tmask[2] | smk[500] | mbar[6]
#define KB_SMEM_FLOATS 13342
__global__ void __launch_bounds__(256, 4) kB(const float* __restrict__ X, const int* __restrict__ mask) {
    extern __shared__ float sm[];
    float* xs = sm;
    float* cpart = sm + 12288;    // 256
    float* pbuf2 = sm + 12544;    // 256: [par][tok][h] duplicated pairs
    float* s_m = sm + 12800;
    float* s_l = sm + 12808;
    float* s_scale = sm + 12816;
    float* s_any = sm + 12832;
    int* s_tmask = (int*)(sm + 12834);
    int* smk = (int*)(sm + 12836);
    uint32_t mb0 = smem_u32(sm + 13336);

    int half = blockIdx.x, b = blockIdx.y;
    int tid = threadIdx.x, w = tid >> 5, lane = tid & 31;
    const float* Xh = X + (size_t)b * (Nn * Dd) + (size_t)half * 500 * Dd;
    const int* mbp = mask + b * Nn + half * 500;
    for (int i = tid; i < 500; i += 256) smk[i] = mbp[i];
    if (tid < 8) { s_m[tid] = NEGINF; s_l[tid] = 0.f; }
    if (tid < 3) mbar_init(mb0 + tid * 8, 1);

    int tg = w >> 2, qh = (w >> 1) & 1, eh = w & 1;
    int e_lo = eh * 256 + (lane << 2);
    // per-head e-pair qt: qtp[hh][0..1] from e_lo..e_lo+3, [2..3] from e_lo+128..
    unsigned long long qtp[4][4];
    {
        const float* Qtb = g_Qt + (size_t)b * 4096;
#pragma unroll
        for (int hh = 0; hh < 4; hh++) {
            int h = qh * 4 + hh;
            ulonglong2 a = *(const ulonglong2*)(Qtb + h * 512 + e_lo);
            ulonglong2 c = *(const ulonglong2*)(Qtb + h * 512 + e_lo + 128);
            qtp[hh][0] = a.x; qtp[hh][1] = a.y;
            qtp[hh][2] = c.x; qtp[hh][3] = c.y;
        }
    }
    unsigned long long ys64[8];
#pragma unroll
    for (int h = 0; h < 8; h++) ys64[h] = 0ULL;

    __syncthreads();
    uint32_t xs_sh = smem_u32(xs);
    if (w == 0) fill8(Xh, smk, xs_sh, mb0, 0, lane);

    for (int t = 0; t < 63; t++) {
        int t0 = t * 8;
        int ntok = (t == 62) ? 4 : 8;
        int s = t % 3, par = t & 1;
        if (w == 0 && t < 62) {
            int ns = (t + 1) % 3;
            fill8(Xh, smk, xs_sh + ns * 16384, mb0 + ns * 8, t + 1, lane);
        }
        mbar_wait(mb0 + s * 8, (t / 3) & 1);
        if (tid == 0) s_any[par] = 0.f;
        const float* xc = xs + s * 4096;
        // ---- phase 2: compat partials (e-pair f32x2, 4-level shuffle) ----
#pragma unroll
        for (int k = 0; k < 4; k++) {
            int n = tg * 4 + k;
            if (n >= ntok || smk[t0 + n]) continue;
            const float* row = xc + (n << 9);
            ulonglong2 xA = *(const ulonglong2*)(row + e_lo);
            ulonglong2 xB = *(const ulonglong2*)(row + e_lo + 128);
            unsigned long long av2[4] = {0, 0, 0, 0};
#pragma unroll
            for (int hh = 0; hh < 4; hh++) {
                ffma2(av2[hh], xA.x, qtp[hh][0]);
                ffma2(av2[hh], xA.y, qtp[hh][1]);
                ffma2(av2[hh], xB.x, qtp[hh][2]);
                ffma2(av2[hh], xB.y, qtp[hh][3]);
            }
            float a0, b0, a1, b1, a2, b2, a3, b3;
            unpack2(av2[0], a0, b0); unpack2(av2[1], a1, b1);
            unpack2(av2[2], a2, b2); unpack2(av2[3], a3, b3);
            a0 += b0; a1 += b1; a2 += b2; a3 += b3;
#pragma unroll
            for (int off = 16; off > 1; off >>= 1) {   // 4 levels: 16,8,4,2
                a0 += __shfl_xor_sync(0xffffffffu, a0, off);
                a1 += __shfl_xor_sync(0xffffffffu, a1, off);
                a2 += __shfl_xor_sync(0xffffffffu, a2, off);
                a3 += __shfl_xor_sync(0xffffffffu, a3, off);
            }
            if (lane < 2)   // lane0 = even-lane sum, lane1 = odd-lane sum
                *(float4*)(cpart + lane * 128 + (eh * 8 + n) * 8 + qh * 4) =
                    make_float4(a0, a1, a2, a3);
        }
        __syncthreads();
        // ---- phase 3: online softmax (warp = head, lanes 0-7 = tokens) ----
        {
            int h = w;
            if (w == 0) {
                unsigned mb2 = __ballot_sync(0xffffffffu,
                    (lane < 8) && ((lane >= ntok) || (smk[t0 + lane] != 0)));
                if (lane == 0) s_tmask[par] = (int)(mb2 & 0xffu);
            }
            float u = NEGINF;
            if (lane < ntok && smk[t0 + lane] == 0)
                u = cpart[lane * 8 + h] + cpart[64 + lane * 8 + h]
                  + cpart[128 + lane * 8 + h] + cpart[192 + lane * 8 + h];
            float tmax = u;
#pragma unroll
            for (int off = 16; off > 0; off >>= 1) tmax = fmaxf(tmax, __shfl_xor_sync(0xffffffffu, tmax, off));
            float m_old = s_m[h], m_new = fmaxf(m_old, tmax);
            float p = (u != NEGINF) ? __expf(u - m_new) : 0.f;
            if (lane < 8)
                *(unsigned long long*)(pbuf2 + par * 128 + lane * 16 + h * 2) = pack2(p, p);
            float ps = p;
#pragma unroll
            for (int off = 16; off > 0; off >>= 1) ps += __shfl_xor_sync(0xffffffffu, ps, off);
            if (lane == 0) {
                float sc = 1.f;
                if (m_new > m_old) { sc = (m_old == NEGINF) ? 1.f : __expf(m_old - m_new); s_m[h] = m_new; }
                s_scale[par * 8 + h] = sc;
                s_l[h] = s_l[h] * sc + ps;
                if (sc != 1.f) s_any[par] = 1.f;
            }
        }
        __syncthreads();
        // ---- phase 4: ysum (pre-duplicated p pairs, tile-mask register) ----
        if (s_any[par] != 0.f) {
#pragma unroll
            for (int h = 0; h < 8; h++) {
                float s2 = s_scale[par * 8 + h];
                fmul2(ys64[h], pack2(s2, s2));
            }
        }
        int tm = s_tmask[par];
        const float* pb2 = pbuf2 + par * 128;
        for (int k = 0; k < ntok; k++) {
            if ((tm >> k) & 1) continue;
            unsigned long long xv = *(const unsigned long long*)(xc + (k << 9) + (tid << 1));
            ulonglong2 pA = *(const ulonglong2*)(pb2 + (k << 4));
            ulonglong2 pB = *(const ulonglong2*)(pb2 + (k << 4) + 4);
            ulonglong2 pC = *(const ulonglong2*)(pb2 + (k << 4) + 8);
            ulonglong2 pD = *(const ulonglong2*)(pb2 + (k << 4) + 12);
            ffma2(ys64[0], xv, pA.x); ffma2(ys64[1], xv, pA.y);
            ffma2(ys64[2], xv, pB.x); ffma2(ys64[3], xv, pB.y);
            ffma2(ys64[4], xv, pC.x); ffma2(ys64[5], xv, pC.y);
            ffma2(ys64[6], xv, pD.x); ffma2(ys64[7], xv, pD.y);
        }
    }
    __syncthreads();
    float* yo = g_ys2 + ((size_t)(half * Bb + b)) * 4096;
#pragma unroll
    for (int h = 0; h < 8; h++) {
        float a, bv;
        unpack2(ys64[h], a, bv);
        *(float2*)(yo + h * 512 + (tid << 1)) = make_float2(a, bv);
    }
    if (tid < 8) {
        g_m2[(half * Bb + b) * 8 + tid] = s_m[tid];
        g_l2[(half * Bb + b) * 8 + tid] = s_l[tid];
    }
}

// =============== kV: merge halves + mhaH = (ysum/l)@Wv ; grid(4,32) x 128, f32x2
__global__ void __launch_bounds__(128) kV(const float* __restrict__ Wv) {
    __shared__ float syc[2 * 4096];
    __shared__ float s0a[16], s1a[16];
    int h0 = blockIdx.x * 2, b0 = blockIdx.y * 8, tid = threadIdx.x;
    if (tid < 16) {
        int bb = tid >> 1, hl = tid & 1;
        int b = b0 + bb, h = h0 + hl;
        float m0 = g_m2[b * 8 + h], m1 = g_m2[(Bb + b) * 8 + h];
        float l0 = g_l2[b * 8 + h], l1 = g_l2[(Bb + b) * 8 + h];
        float M = fmaxf(m0, m1);
        float e0 = __expf(m0 - M), e1 = __expf(m1 - M);
        float L = l0 * e0 + l1 * e1;
        s0a[tid] = e0 / L;
        s1a[tid] = e1 / L;
    }
    __syncthreads();
    for (int i = tid; i < 8192; i += 128) {
        int hl = i >> 12, bb = (i >> 9) & 7, e = i & 511;
        int b = b0 + bb, h = h0 + hl;
        float v = g_ys2[(size_t)b * 4096 + h * 512 + e] * s0a[bb * 2 + hl]
                + g_ys2[(size_t)(Bb + b) * 4096 + h * 512 + e] * s1a[bb * 2 + hl];
        syc[hl * 4096 + e * 8 + bb] = v;
    }
    __syncthreads();
    int j = blockIdx.x * 128 + tid, hl = tid >> 6;
    const float* base = syc + hl * 4096;
    unsigned long long acc[4] = {0ULL, 0ULL, 0ULL, 0ULL};
    for (int e = 0; e < 512; e++) {
        float wv = Wv[e * Dd + j];
        unsigned long long ww = pack2(wv, wv);
        ulonglong2 y0 = *(const ulonglong2*)(base + e * 8);
        ulonglong2 y1 = *(const ulonglong2*)(base + e * 8 + 4);
        ffma2(acc[0], y0.x, ww); ffma2(acc[1], y0.y, ww);
        ffma2(acc[2], y1.x, ww); ffma2(acc[3], y1.y, ww);
    }
#pragma unroll
    for (int p = 0; p < 4; p++) {
        float a, b;
        unpack2(acc[p], a, b);
        g_mhaH[(b0 + 2 * p) * Dd + j] = a;
        g_mhaH[(b0 + 2 * p + 1) * Dd + j] = b;
    }
}

// =============== kZ: z = norm_ptr * Wkp@mo ; grid(4,32) x 128, f32x2
__global__ void __launch_bounds__(128) kZ(const float* __restrict__ Wkp) {
    __shared__ float smo[512 * 8];
    int e0 = blockIdx.x * 128, b0 = blockIdx.y * 8, tid = threadIdx.x;
    for (int i = tid; i < 4096; i += 128) smo[(i & 511) * 8 + (i >> 9)] = g_mo[(b0 + (i >> 9)) * Dd + (i & 511)];
    __syncthreads();
    int e = e0 + tid;
    const float* wrow = Wkp + (size_t)e * Dd;
    unsigned long long acc[4] = {0ULL, 0ULL, 0ULL, 0ULL};
    for (int f = 0; f < 512; f++) {
        float wv = wrow[f];
        unsigned long long ww = pack2(wv, wv);
        ulonglong2 m0 = *(const ulonglong2*)(smo + f * 8);
        ulonglong2 m1 = *(const ulonglong2*)(smo + f * 8 + 4);
        ffma2(acc[0], m0.x, ww); ffma2(acc[1], m0.y, ww);
        ffma2(acc[2], m1.x, ww); ffma2(acc[3], m1.y, ww);
    }
#pragma unroll
    for (int p = 0; p < 4; p++) {
        float a, b;
        unpack2(acc[p], a, b);
        g_z[(b0 + 2 * p) * Dd + e] = a * NORM_PTR;
        g_z[(b0 + 2 * p + 1) * Dd + e] = b * NORM_PTR;
    }
}

// =============== kD1: tv = tanh(x.z)*10 ; grid(4,256) x 256 ; 4 rows/warp-group
__global__ void __launch_bounds__(256) kD1(const float* __restrict__ X, const int* __restrict__ mask) {
    __shared__ int smk[250];
    int q = blockIdx.x, b = blockIdx.y;
    int tid = threadIdx.x, w = tid >> 5, lane = tid & 31;
    const int* mbp = mask + b * Nn + q * 250;
    for (int i = tid; i < 250; i += 256) smk[i] = mbp[i];
    const float* zb = g_z + b * Dd;
    float4 z[4];
#pragma unroll
    for (int c = 0; c < 4; c++) z[c] = *(const float4*)(zb + c * 128 + lane * 4);
    const float* Xq = X + (size_t)b * (Nn * Dd) + (size_t)q * 250 * Dd;
    float* tvq = g_tv + b * Nn + q * 250;
    __syncthreads();
    for (int g = w; g < 63; g += 8) {
        int n0 = g * 4;
        int nr = (g == 62) ? 2 : 4;
        int m[4];
        float acc[4] = {0.f, 0.f, 0.f, 0.f};
#pragma unroll
        for (int r = 0; r < 4; r++) m[r] = (r < nr) ? smk[n0 + r] : 1;
#pragma unroll
        for (int c = 0; c < 4; c++) {
            float4 xr[4];
#pragma unroll
            for (int r = 0; r < 4; r++)
                if (!m[r]) xr[r] = *(const float4*)(Xq + (size_t)(n0 + r) * Dd + c * 128 + lane * 4);
#pragma unroll
            for (int r = 0; r < 4; r++)
                if (!m[r])
                    acc[r] += xr[r].x * z[c].x + xr[r].y * z[c].y + xr[r].z * z[c].z + xr[r].w * z[c].w;
        }
#pragma unroll
        for (int off = 16; off > 0; off >>= 1) {
#pragma unroll
            for (int r = 0; r < 4; r++) acc[r] += __shfl_xor_sync(0xffffffffu, acc[r], off);
        }
        if (lane == 0) {
#pragma unroll
            for (int r = 0; r < 4; r++)
                if (r < nr) tvq[n0 + r] = m[r] ? NEGINF : tanhf(acc[r]) * 10.f;
        }
    }
}

// =============== kD2: masked softmax over tv ; grid 256 x 512
__global__ void __launch_bounds__(512) kD2(float* __restrict__ out) {
    __shared__ float tvals[Nn];
    __shared__ float red[16];
    __shared__ float bcv;
    int b = blockIdx.x, tid = threadIdx.x, w = tid >> 5, lane = tid & 31;
    const float* tvg = g_tv + b * Nn;
    for (int i = tid; i < Nn; i += 512) tvals[i] = tvg[i];
    __syncthreads();
    float t0v = tvals[tid];
    int n1 = tid + 512;
    float t1v = (n1 < Nn) ? tvals[n1] : NEGINF;
    float wmax = fmaxf(t0v, t1v);
#pragma unroll
    for (int off = 16; off > 0; off >>= 1) wmax = fmaxf(wmax, __shfl_xor_sync(0xffffffffu, wmax, off));
    if (lane == 0) red[w] = wmax;
    __syncthreads();
    if (tid == 0) {
        float m = red[0];
#pragma unroll
        for (int i = 1; i < 16; i++) m = fmaxf(m, red[i]);
        bcv = m;
    }
    __syncthreads();
    float gmax = bcv;
    float ev0 = (t0v == NEGINF) ? 0.f : __expf(t0v - gmax);
    float ev1 = (t1v == NEGINF) ? 0.f : __expf(t1v - gmax);
    float ps = ev0 + ev1;
#pragma unroll
    for (int off = 16; off > 0; off >>= 1) ps += __shfl_xor_sync(0xffffffffu, ps, off);
    __syncthreads();
    if (lane == 0) red[w] = ps;
    __syncthreads();
    if (tid == 0) {
        float s = 0.f;
#pragma unroll
        for (int i = 0; i < 16; i++) s += red[i];
        bcv = 1.f / s;
    }
    __syncthreads();
    float inv = bcv;
    out[b * Nn + tid] = ev0 * inv;
    if (n1 < Nn) out[b * Nn + n1] = ev1 * inv;
}

extern "C" void kernel_launch(void* const* d_in, const int* in_sizes, int n_in,
                              void* d_out, int out_size) {
    const float* X    = (const float*)d_in[0];
    const float* pool = (const float*)d_in[1];
    const float* dc   = (const float*)d_in[2];
    const int*   mask = (const int*)d_in[3];
    const float* Wfc  = (const float*)d_in[4];
    const float* Wfc1 = (const float*)d_in[5];
    const float* Wq   = (const float*)d_in[6];
    const float* Wkm  = (const float*)d_in[7];
    const float* Wv   = (const float*)d_in[8];
    const float* Wo   = (const float*)d_in[9];
    const float* Wkp  = (const float*)d_in[10];
    float* out = (float*)d_out;
    const int KB_SMEM = KB_SMEM_FLOATS * 4;
    cudaFuncSetAttribute(kB, cudaFuncAttributeMaxDynamicSharedMemorySize, KB_SMEM);
    kS<<<dim3(4, 32), 128>>>(X, pool, dc, Wfc, Wfc1);
    kMM<<<dim3(4, 32), 128>>>(Wq, 0);
    kQt<<<dim3(4, 32), 128>>>(Wkm);
    kB<<<dim3(2, 256), 256, KB_SMEM>>>(X, mask);
    kV<<<dim3(4, 32), 128>>>(Wv);
    kMM<<<dim3(4, 32), 128>>>(Wo, 1);
    kZ<<<dim3(4, 32), 128>>>(Wkp);
    kD1<<<dim3(4, 256), 256>>>(X, mask);
    kD2<<<256, 512>>>(out);
}

// round 15
// speedup vs baseline: 1.1034x; 1.1034x over previous
#include <cuda_runtime.h>
#include <math.h>
#include <stdint.h>

#define Bb 256
#define Nn 1000
#define Dd 512
#define NEGINF (-INFINITY)
#define NORM_MHA 0.125f
#define NORM_PTR 0.04419417382415922f

static __device__ float g_state[Bb * Dd];
static __device__ float g_Qf[Bb * Dd];
static __device__ float g_Qt[Bb * 8 * Dd];
static __device__ float g_ys2[2 * Bb * 8 * Dd];
static __device__ float g_m2[2 * Bb * 8];
static __device__ float g_l2[2 * Bb * 8];
static __device__ float g_mhaH[Bb * Dd];
static __device__ float g_mo[Bb * Dd];
static __device__ float g_z[Bb * Dd];
static __device__ float g_tv[Bb * Nn];

// ---------- f32x2 helpers ----------
__device__ __forceinline__ unsigned long long pack2(float a, float b) {
    unsigned long long r;
    asm("mov.b64 %0,{%1,%2};" : "=l"(r) : "f"(a), "f"(b));
    return r;
}
__device__ __forceinline__ void unpack2(unsigned long long v, float& a, float& b) {
    asm("mov.b64 {%0,%1},%2;" : "=f"(a), "=f"(b) : "l"(v));
}
__device__ __forceinline__ void ffma2(unsigned long long& d, unsigned long long a, unsigned long long b) {
    asm("fma.rn.f32x2 %0,%1,%2,%0;" : "+l"(d) : "l"(a), "l"(b));
}
__device__ __forceinline__ void fmul2(unsigned long long& d, unsigned long long a) {
    asm("mul.rn.f32x2 %0,%0,%1;" : "+l"(d) : "l"(a));
}

// ---------- mbarrier + bulk-copy helpers ----------
__device__ __forceinline__ uint32_t smem_u32(const void* p) {
    return (uint32_t)__cvta_generic_to_shared(p);
}
__device__ __forceinline__ void mbar_init(uint32_t a, uint32_t c) {
    asm volatile("mbarrier.init.shared.b64 [%0],%1;" ::"r"(a), "r"(c) : "memory");
}
__device__ __forceinline__ void mbar_expect(uint32_t a, uint32_t bytes) {
    asm volatile("mbarrier.arrive.expect_tx.shared.b64 _,[%0],%1;" ::"r"(a), "r"(bytes) : "memory");
}
__device__ __forceinline__ void mbar_wait(uint32_t a, uint32_t phase) {
    asm volatile(
        "{\n\t.reg .pred P;\n\t"
        "WL%=:\n\t"
        "mbarrier.try_wait.parity.acquire.cta.shared::cta.b64 P,[%0],%1,0x989680;\n\t"
        "@P bra WD%=;\n\t"
        "bra WL%=;\n\t"
        "WD%=:\n\t}"
        ::"r"(a), "r"(phase) : "memory");
}
__device__ __forceinline__ void bulkcp(uint32_t dsh, const void* g, uint32_t n, uint32_t mb) {
    asm volatile("cp.async.bulk.shared::cta.global.mbarrier::complete_tx::bytes [%0],[%1],%2,[%3];"
                 ::"r"(dsh), "l"(g), "r"(n), "r"(mb) : "memory");
}

__device__ __forceinline__ void fill8(const float* __restrict__ Xh, const int* __restrict__ smk,
                                      uint32_t dsh, uint32_t mb, int t, int lane) {
    int ntok = (t == 62) ? 4 : 8;
    int tok = t * 8 + lane;
    bool act = (lane < ntok) && (smk[tok] == 0);
    unsigned bal = __ballot_sync(0xffffffffu, act);
    int cnt = __popc(bal);
    if (cnt == 0) {
        if (lane == 0) {
            mbar_expect(mb, 2048);
            bulkcp(dsh, Xh + (size_t)t * 8 * 512, 2048, mb);
        }
    } else {
        if (lane == 0) mbar_expect(mb, (uint32_t)cnt * 2048);
        __syncwarp();
        if (act) bulkcp(dsh + lane * 2048, Xh + (size_t)tok * 512, 2048, mb);
    }
}

// =============== kS: state = [x0,dc]@W_fc + pool@W_fc1 ; grid(4,32) x 256 (batch-split)
__global__ void __launch_bounds__(256) kS(const float* __restrict__ X, const float* __restrict__ pool,
                                          const float* __restrict__ dc, const float* __restrict__ Wfc,
                                          const float* __restrict__ Wfc1) {
    __shared__ float sx[512 * 8], sp[512 * 8], sdc[8];
    int j0 = blockIdx.x * 128, b0 = blockIdx.y * 8, tid = threadIdx.x;
    for (int i = tid; i < 4096; i += 256) {
        int bb = i >> 9, e = i & 511;
        sx[e * 8 + bb] = X[(size_t)(b0 + bb) * (Nn * Dd) + e];
        sp[e * 8 + bb] = pool[(b0 + bb) * Dd + e];
    }
    if (tid < 8) sdc[tid] = dc[b0 + tid];
    __syncthreads();
    int jt = tid & 127, th = tid >> 7;
    int j = j0 + jt;
    unsigned long long acc[2] = {0ULL, 0ULL};
    for (int e = 0; e < 512; e++) {
        float w0 = Wfc[e * Dd + j], w1 = Wfc1[e * Dd + j];
        unsigned long long w00 = pack2(w0, w0), w11 = pack2(w1, w1);
        ulonglong2 a = *(const ulonglong2*)(sx + e * 8 + th * 4);
        ulonglong2 c = *(const ulonglong2*)(sp + e * 8 + th * 4);
        ffma2(acc[0], a.x, w00); ffma2(acc[0], c.x, w11);
        ffma2(acc[1], a.y, w00); ffma2(acc[1], c.y, w11);
    }
    float wl = Wfc[512 * Dd + j];
#pragma unroll
    for (int p = 0; p < 2; p++) {
        float a, b;
        unpack2(acc[p], a, b);
        int bbase = b0 + th * 4 + 2 * p;
        g_state[bbase * Dd + j] = a + sdc[th * 4 + 2 * p] * wl;
        g_state[(bbase + 1) * Dd + j] = b + sdc[th * 4 + 2 * p + 1] * wl;
    }
}

// =============== kMM: Out = A@W ; grid(4,32) x 256 (batch-split)
__global__ void __launch_bounds__(256) kMM(const float* __restrict__ W, int mode) {
    __shared__ float sa[512 * 8];
    const float* A = mode ? g_mhaH : g_state;
    float* Out = mode ? g_mo : g_Qf;
    int j0 = blockIdx.x * 128, b0 = blockIdx.y * 8, tid = threadIdx.x;
    for (int i = tid; i < 4096; i += 256) sa[(i & 511) * 8 + (i >> 9)] = A[(b0 + (i >> 9)) * Dd + (i & 511)];
    __syncthreads();
    int jt = tid & 127, th = tid >> 7;
    int j = j0 + jt;
    unsigned long long acc[2] = {0ULL, 0ULL};
    for (int f = 0; f < 512; f++) {
        float wv = W[f * Dd + j];
        unsigned long long ww = pack2(wv, wv);
        ulonglong2 a = *(const ulonglong2*)(sa + f * 8 + th * 4);
        ffma2(acc[0], a.x, ww); ffma2(acc[1], a.y, ww);
    }
#pragma unroll
    for (int p = 0; p < 2; p++) {
        float a, b;
        unpack2(acc[p], a, b);
        int bbase = b0 + th * 4 + 2 * p;
        Out[bbase * Dd + j] = a;
        Out[(bbase + 1) * Dd + j] = b;
    }
}

// =============== kQt: Qt[b][h][e] ; grid(4,32) x 256 (head-split)
__global__ void __launch_bounds__(256) kQt(const float* __restrict__ Wk) {
    __shared__ float sq[8 * 512];
    int e0 = blockIdx.x * 128, b0 = blockIdx.y * 8, tid = threadIdx.x;
    for (int i = tid; i < 4096; i += 256) sq[i] = g_Qf[(b0 + (i >> 9)) * Dd + (i & 511)];
    __syncthreads();
    int jt = tid & 127, th = tid >> 7;
    int e = e0 + jt;
    const float* wrow = Wk + (size_t)e * Dd;
    for (int h = th * 4; h < th * 4 + 4; h++) {
        unsigned long long accp[8];
#pragma unroll
        for (int k = 0; k < 8; k++) accp[k] = 0ULL;
        const float* wr = wrow + h * 64;
#pragma unroll
        for (int d4 = 0; d4 < 16; d4++) {
            float4 wv = *(const float4*)(wr + d4 * 4);
            unsigned long long w01 = pack2(wv.x, wv.y), w23 = pack2(wv.z, wv.w);
#pragma unroll
            for (int bb = 0; bb < 8; bb++) {
                ulonglong2 q2 = *(const ulonglong2*)(sq + bb * 512 + h * 64 + d4 * 4);
                ffma2(accp[bb], w01, q2.x);
                ffma2(accp[bb], w23, q2.y);
            }
        }
#pragma unroll
        for (int bb = 0; bb < 8; bb++) {
            float a, b;
            unpack2(accp[bb], a, b);
            g_Qt[(size_t)(b0 + bb) * 4096 + h * 512 + e] = (a + b) * NORM_MHA;
        }
    }
}

// =============== kB: pass 1, half-batch CTAs (grid (2,256) x 256) — R11 proven version
#define KB_SMEM_FLOATS 13086
__global__ void __launch_bounds__(256, 4) kB(const float* __restrict__ X, const int* __restrict__ mask) {
    extern __shared__ float sm[];
    float* xs = sm;
    float* cpart = sm + 12288;
    float* pbuf = sm + 12416;
    float* s_m = sm + 12544;
    float* s_l = sm + 12552;
    float* s_scale = sm + 12560;
    float* s_any = sm + 12576;
    int* smk = (int*)(sm + 12580);
    uint32_t mb0 = smem_u32(sm + 13080);

    int half = blockIdx.x, b = blockIdx.y;
    int tid = threadIdx.x, w = tid >> 5, lane = tid & 31;
    const float* Xh = X + (size_t)b * (Nn * Dd) + (size_t)half * 500 * Dd;
    const int* mbp = mask + b * Nn + half * 500;
    for (int i = tid; i < 500; i += 256) smk[i] = mbp[i];
    if (tid < 8) { s_m[tid] = NEGINF; s_l[tid] = 0.f; }
    if (tid < 3) mbar_init(mb0 + tid * 8, 1);

    int tg = w >> 2, qh = (w >> 1) & 1, eh = w & 1;
    int e_lo = eh * 256 + (lane << 2);
    unsigned long long qt2[2][8];
    {
        const float* Qtb = g_Qt + (size_t)b * 4096;
        float qv[4][8];
#pragma unroll
        for (int hh = 0; hh < 4; hh++) {
            int h = qh * 4 + hh;
            float4 a = *(const float4*)(Qtb + h * 512 + e_lo);
            float4 c = *(const float4*)(Qtb + h * 512 + e_lo + 128);
            qv[hh][0] = a.x; qv[hh][1] = a.y; qv[hh][2] = a.z; qv[hh][3] = a.w;
            qv[hh][4] = c.x; qv[hh][5] = c.y; qv[hh][6] = c.z; qv[hh][7] = c.w;
        }
#pragma unroll
        for (int e = 0; e < 8; e++) {
            qt2[0][e] = pack2(qv[0][e], qv[1][e]);
            qt2[1][e] = pack2(qv[2][e], qv[3][e]);
        }
    }
    unsigned long long ys64[8];
#pragma unroll
    for (int h = 0; h < 8; h++) ys64[h] = 0ULL;

    __syncthreads();
    uint32_t xs_sh = smem_u32(xs);
    if (w == 0) fill8(Xh, smk, xs_sh, mb0, 0, lane);

    for (int t = 0; t < 63; t++) {
        int t0 = t * 8;
        int ntok = (t == 62) ? 4 : 8;
        int s = t % 3, par = t & 1;
        if (w == 0 && t < 62) {
            int ns = (t + 1) % 3;
            fill8(Xh, smk, xs_sh + ns * 16384, mb0 + ns * 8, t + 1, lane);
        }
        mbar_wait(mb0 + s * 8, (t / 3) & 1);
        if (tid == 0) s_any[par] = 0.f;
        const float* xc = xs + s * 4096;
#pragma unroll
        for (int k = 0; k < 4; k++) {
            int n = tg * 4 + k;
            if (n >= ntok || smk[t0 + n]) continue;
            const float* row = xc + (n << 9);
            float4 xa = *(const float4*)(row + e_lo);
            float4 xb2 = *(const float4*)(row + e_lo + 128);
            unsigned long long av0 = 0, av1 = 0, xx;
            xx = pack2(xa.x, xa.x); ffma2(av0, xx, qt2[0][0]); ffma2(av1, xx, qt2[1][0]);
            xx = pack2(xa.y, xa.y); ffma2(av0, xx, qt2[0][1]); ffma2(av1, xx, qt2[1][1]);
            xx = pack2(xa.z, xa.z); ffma2(av0, xx, qt2[0][2]); ffma2(av1, xx, qt2[1][2]);
            xx = pack2(xa.w, xa.w); ffma2(av0, xx, qt2[0][3]); ffma2(av1, xx, qt2[1][3]);
            xx = pack2(xb2.x, xb2.x); ffma2(av0, xx, qt2[0][4]); ffma2(av1, xx, qt2[1][4]);
            xx = pack2(xb2.y, xb2.y); ffma2(av0, xx, qt2[0][5]); ffma2(av1, xx, qt2[1][5]);
            xx = pack2(xb2.z, xb2.z); ffma2(av0, xx, qt2[0][6]); ffma2(av1, xx, qt2[1][6]);
            xx = pack2(xb2.w, xb2.w); ffma2(av0, xx, qt2[0][7]); ffma2(av1, xx, qt2[1][7]);
            float a0, a1, a2, a3;
            unpack2(av0, a0, a1); unpack2(av1, a2, a3);
#pragma unroll
            for (int off = 16; off > 0; off >>= 1) {
                a0 += __shfl_xor_sync(0xffffffffu, a0, off);
                a1 += __shfl_xor_sync(0xffffffffu, a1, off);
                a2 += __shfl_xor_sync(0xffffffffu, a2, off);
                a3 += __shfl_xor_sync(0xffffffffu, a3, off);
            }
            if (lane == 0)
                *(float4*)(cpart + (eh * 8 + n) * 8 + qh * 4) = make_float4(a0, a1, a2, a3);
        }
        __syncthreads();
        {
            int h = w;
            float u = NEGINF;
            if (lane < ntok && smk[t0 + lane] == 0) u = cpart[lane * 8 + h] + cpart[64 + lane * 8 + h];
            float tmax = u;
#pragma unroll
            for (int off = 16; off > 0; off >>= 1) tmax = fmaxf(tmax, __shfl_xor_sync(0xffffffffu, tmax, off));
            float m_old = s_m[h], m_new = fmaxf(m_old, tmax);
            float p = (u != NEGINF) ? __expf(u - m_new) : 0.f;
            if (lane < 8) pbuf[par * 64 + lane * 8 + h] = p;
            float ps = p;
#pragma unroll
            for (int off = 16; off > 0; off >>= 1) ps += __shfl_xor_sync(0xffffffffu, ps, off);
            if (lane == 0) {
                float sc = 1.f;
                if (m_new > m_old) { sc = (m_old == NEGINF) ? 1.f : __expf(m_old - m_new); s_m[h] = m_new; }
                s_scale[par * 8 + h] = sc;
                s_l[h] = s_l[h] * sc + ps;
                if (sc != 1.f) s_any[par] = 1.f;
            }
        }
        __syncthreads();
        if (s_any[par] != 0.f) {
#pragma unroll
            for (int h = 0; h < 8; h++) {
                float s2 = s_scale[par * 8 + h];
                fmul2(ys64[h], pack2(s2, s2));
            }
        }
        const float* pb = pbuf + par * 64;
        for (int k = 0; k < ntok; k++) {
            if (smk[t0 + k]) continue;
            unsigned long long xv = *(const unsigned long long*)(xc + (k << 9) + (tid << 1));
            float4 p0 = *(const float4*)(pb + (k << 3));
            float4 p1 = *(const float4*)(pb + (k << 3) + 4);
            ffma2(ys64[0], xv, pack2(p0.x, p0.x));
            ffma2(ys64[1], xv, pack2(p0.y, p0.y));
            ffma2(ys64[2], xv, pack2(p0.z, p0.z));
            ffma2(ys64[3], xv, pack2(p0.w, p0.w));
            ffma2(ys64[4], xv, pack2(p1.x, p1.x));
            ffma2(ys64[5], xv, pack2(p1.y, p1.y));
            ffma2(ys64[6], xv, pack2(p1.z, p1.z));
            ffma2(ys64[7], xv, pack2(p1.w, p1.w));
        }
    }
    __syncthreads();
    float* yo = g_ys2 + ((size_t)(half * Bb + b)) * 4096;
#pragma unroll
    for (int h = 0; h < 8; h++) {
        float a, bv;
        unpack2(ys64[h], a, bv);
        *(float2*)(yo + h * 512 + (tid << 1)) = make_float2(a, bv);
    }
    if (tid < 8) {
        g_m2[(half * Bb + b) * 8 + tid] = s_m[tid];
        g_l2[(half * Bb + b) * 8 + tid] = s_l[tid];
    }
}

// =============== kV: merge halves + mhaH = (ysum/l)@Wv ; grid(4,32) x 256 (batch-split)
__global__ void __launch_bounds__(256) kV(const float* __restrict__ Wv) {
    __shared__ float syc[2 * 4096];
    __shared__ float s0a[16], s1a[16];
    int h0 = blockIdx.x * 2, b0 = blockIdx.y * 8, tid = threadIdx.x;
    if (tid < 16) {
        int bb = tid >> 1, hl = tid & 1;
        int b = b0 + bb, h = h0 + hl;
        float m0 = g_m2[b * 8 + h], m1 = g_m2[(Bb + b) * 8 + h];
        float l0 = g_l2[b * 8 + h], l1 = g_l2[(Bb + b) * 8 + h];
        float M = fmaxf(m0, m1);
        float e0 = __expf(m0 - M), e1 = __expf(m1 - M);
        float L = l0 * e0 + l1 * e1;
        s0a[tid] = e0 / L;
        s1a[tid] = e1 / L;
    }
    __syncthreads();
    for (int i = tid; i < 8192; i += 256) {
        int hl = i >> 12, bb = (i >> 9) & 7, e = i & 511;
        int b = b0 + bb, h = h0 + hl;
        float v = g_ys2[(size_t)b * 4096 + h * 512 + e] * s0a[bb * 2 + hl]
                + g_ys2[(size_t)(Bb + b) * 4096 + h * 512 + e] * s1a[bb * 2 + hl];
        syc[hl * 4096 + e * 8 + bb] = v;
    }
    __syncthreads();
    int jt = tid & 127, th = tid >> 7;
    int j = blockIdx.x * 128 + jt, hl = jt >> 6;
    const float* base = syc + hl * 4096;
    unsigned long long acc[2] = {0ULL, 0ULL};
    for (int e = 0; e < 512; e++) {
        float wv = Wv[e * Dd + j];
        unsigned long long ww = pack2(wv, wv);
        ulonglong2 y = *(const ulonglong2*)(base + e * 8 + th * 4);
        ffma2(acc[0], y.x, ww); ffma2(acc[1], y.y, ww);
    }
#pragma unroll
    for (int p = 0; p < 2; p++) {
        float a, b;
        unpack2(acc[p], a, b);
        int bbase = b0 + th * 4 + 2 * p;
        g_mhaH[bbase * Dd + j] = a;
        g_mhaH[(bbase + 1) * Dd + j] = b;
    }
}

// =============== kZ: z = norm_ptr * Wkp@mo ; grid(4,32) x 256 (batch-split)
__global__ void __launch_bounds__(256) kZ(const float* __restrict__ Wkp) {
    __shared__ float smo[512 * 8];
    int e0 = blockIdx.x * 128, b0 = blockIdx.y * 8, tid = threadIdx.x;
    for (int i = tid; i < 4096; i += 256) smo[(i & 511) * 8 + (i >> 9)] = g_mo[(b0 + (i >> 9)) * Dd + (i & 511)];
    __syncthreads();
    int jt = tid & 127, th = tid >> 7;
    int e = e0 + jt;
    const float* wrow = Wkp + (size_t)e * Dd;
    unsigned long long acc[2] = {0ULL, 0ULL};
    for (int f = 0; f < 512; f++) {
        float wv = wrow[f];
        unsigned long long ww = pack2(wv, wv);
        ulonglong2 m = *(const ulonglong2*)(smo + f * 8 + th * 4);
        ffma2(acc[0], m.x, ww); ffma2(acc[1], m.y, ww);
    }
#pragma unroll
    for (int p = 0; p < 2; p++) {
        float a, b;
        unpack2(acc[p], a, b);
        int bbase = b0 + th * 4 + 2 * p;
        g_z[bbase * Dd + e] = a * NORM_PTR;
        g_z[(bbase + 1) * Dd + e] = b * NORM_PTR;
    }
}

// =============== kD1: tv = tanh(x.z)*10 ; grid(4,256) x 256 ; 4 rows/warp-group
__global__ void __launch_bounds__(256) kD1(const float* __restrict__ X, const int* __restrict__ mask) {
    __shared__ int smk[250];
    int q = blockIdx.x, b = blockIdx.y;
    int tid = threadIdx.x, w = tid >> 5, lane = tid & 31;
    const int* mbp = mask + b * Nn + q * 250;
    for (int i = tid; i < 250; i += 256) smk[i] = mbp[i];
    const float* zb = g_z + b * Dd;
    float4 z[4];
#pragma unroll
    for (int c = 0; c < 4; c++) z[c] = *(const float4*)(zb + c * 128 + lane * 4);
    const float* Xq = X + (size_t)b * (Nn * Dd) + (size_t)q * 250 * Dd;
    float* tvq = g_tv + b * Nn + q * 250;
    __syncthreads();
    for (int g = w; g < 63; g += 8) {
        int n0 = g * 4;
        int nr = (g == 62) ? 2 : 4;
        int m[4];
        float acc[4] = {0.f, 0.f, 0.f, 0.f};
#pragma unroll
        for (int r = 0; r < 4; r++) m[r] = (r < nr) ? smk[n0 + r] : 1;
#pragma unroll
        for (int c = 0; c < 4; c++) {
            float4 xr[4];
#pragma unroll
            for (int r = 0; r < 4; r++)
                if (!m[r]) xr[r] = *(const float4*)(Xq + (size_t)(n0 + r) * Dd + c * 128 + lane * 4);
#pragma unroll
            for (int r = 0; r < 4; r++)
                if (!m[r])
                    acc[r] += xr[r].x * z[c].x + xr[r].y * z[c].y + xr[r].z * z[c].z + xr[r].w * z[c].w;
        }
#pragma unroll
        for (int off = 16; off > 0; off >>= 1) {
#pragma unroll
            for (int r = 0; r < 4; r++) acc[r] += __shfl_xor_sync(0xffffffffu, acc[r], off);
        }
        if (lane == 0) {
#pragma unroll
            for (int r = 0; r < 4; r++)
                if (r < nr) tvq[n0 + r] = m[r] ? NEGINF : tanhf(acc[r]) * 10.f;
        }
    }
}

// =============== kD2: masked softmax over tv ; grid 256 x 512
__global__ void __launch_bounds__(512) kD2(float* __restrict__ out) {
    __shared__ float tvals[Nn];
    __shared__ float red[16];
    __shared__ float bcv;
    int b = blockIdx.x, tid = threadIdx.x, w = tid >> 5, lane = tid & 31;
    const float* tvg = g_tv + b * Nn;
    for (int i = tid; i < Nn; i += 512) tvals[i] = tvg[i];
    __syncthreads();
    float t0v = tvals[tid];
    int n1 = tid + 512;
    float t1v = (n1 < Nn) ? tvals[n1] : NEGINF;
    float wmax = fmaxf(t0v, t1v);
#pragma unroll
    for (int off = 16; off > 0; off >>= 1) wmax = fmaxf(wmax, __shfl_xor_sync(0xffffffffu, wmax, off));
    if (lane == 0) red[w] = wmax;
    __syncthreads();
    if (tid == 0) {
        float m = red[0];
#pragma unroll
        for (int i = 1; i < 16; i++) m = fmaxf(m, red[i]);
        bcv = m;
    }
    __syncthreads();
    float gmax = bcv;
    float ev0 = (t0v == NEGINF) ? 0.f : __expf(t0v - gmax);
    float ev1 = (t1v == NEGINF) ? 0.f : __expf(t1v - gmax);
    float ps = ev0 + ev1;
#pragma unroll
    for (int off = 16; off > 0; off >>= 1) ps += __shfl_xor_sync(0xffffffffu, ps, off);
    __syncthreads();
    if (lane == 0) red[w] = ps;
    __syncthreads();
    if (tid == 0) {
        float s = 0.f;
#pragma unroll
        for (int i = 0; i < 16; i++) s += red[i];
        bcv = 1.f / s;
    }
    __syncthreads();
    float inv = bcv;
    out[b * Nn + tid] = ev0 * inv;
    if (n1 < Nn) out[b * Nn + n1] = ev1 * inv;
}

extern "C" void kernel_launch(void* const* d_in, const int* in_sizes, int n_in,
                              void* d_out, int out_size) {
    const float* X    = (const float*)d_in[0];
    const float* pool = (const float*)d_in[1];
    const float* dc   = (const float*)d_in[2];
    const int*   mask = (const int*)d_in[3];
    const float* Wfc  = (const float*)d_in[4];
    const float* Wfc1 = (const float*)d_in[5];
    const float* Wq   = (const float*)d_in[6];
    const float* Wkm  = (const float*)d_in[7];
    const float* Wv   = (const float*)d_in[8];
    const float* Wo   = (const float*)d_in[9];
    const float* Wkp  = (const float*)d_in[10];
    float* out = (float*)d_out;
    const int KB_SMEM = KB_SMEM_FLOATS * 4;
    cudaFuncSetAttribute(kB, cudaFuncAttributeMaxDynamicSharedMemorySize, KB_SMEM);
    kS<<<dim3(4, 32), 256>>>(X, pool, dc, Wfc, Wfc1);
    kMM<<<dim3(4, 32), 256>>>(Wq, 0);
    kQt<<<dim3(4, 32), 256>>>(Wkm);
    kB<<<dim3(2, 256), 256, KB_SMEM>>>(X, mask);
    kV<<<dim3(4, 32), 256>>>(Wv);
    kMM<<<dim3(4, 32), 256>>>(Wo, 1);
    kZ<<<dim3(4, 32), 256>>>(Wkp);
    kD1<<<dim3(4, 256), 256>>>(X, mask);
    kD2<<<256, 512>>>(out);
}

// round 16
// speedup vs baseline: 1.2290x; 1.1139x over previous
#include <cuda_runtime.h>
#include <math.h>
#include <stdint.h>

#define Bb 256
#define Nn 1000
#define Dd 512
#define NEGINF (-INFINITY)
#define NORM_MHA 0.125f
#define NORM_PTR 0.04419417382415922f

static __device__ float g_state[Bb * Dd];
static __device__ float g_Qf[Bb * Dd];
static __device__ float g_Qt[Bb * 8 * Dd];
static __device__ float g_ys2[2 * Bb * 8 * Dd];
static __device__ float g_m2[2 * Bb * 8];
static __device__ float g_l2[2 * Bb * 8];
static __device__ float g_mhaH[Bb * Dd];
static __device__ float g_mo[Bb * Dd];
static __device__ float g_z[Bb * Dd];
static __device__ float g_tv[Bb * Nn];

// ---------- f32x2 helpers ----------
__device__ __forceinline__ unsigned long long pack2(float a, float b) {
    unsigned long long r;
    asm("mov.b64 %0,{%1,%2};" : "=l"(r) : "f"(a), "f"(b));
    return r;
}
__device__ __forceinline__ void unpack2(unsigned long long v, float& a, float& b) {
    asm("mov.b64 {%0,%1},%2;" : "=f"(a), "=f"(b) : "l"(v));
}
__device__ __forceinline__ void ffma2(unsigned long long& d, unsigned long long a, unsigned long long b) {
    asm("fma.rn.f32x2 %0,%1,%2,%0;" : "+l"(d) : "l"(a), "l"(b));
}
__device__ __forceinline__ void fmul2(unsigned long long& d, unsigned long long a) {
    asm("mul.rn.f32x2 %0,%0,%1;" : "+l"(d) : "l"(a));
}

// ---------- mbarrier + bulk-copy helpers ----------
__device__ __forceinline__ uint32_t smem_u32(const void* p) {
    return (uint32_t)__cvta_generic_to_shared(p);
}
__device__ __forceinline__ void mbar_init(uint32_t a, uint32_t c) {
    asm volatile("mbarrier.init.shared.b64 [%0],%1;" ::"r"(a), "r"(c) : "memory");
}
__device__ __forceinline__ void mbar_expect(uint32_t a, uint32_t bytes) {
    asm volatile("mbarrier.arrive.expect_tx.shared.b64 _,[%0],%1;" ::"r"(a), "r"(bytes) : "memory");
}
__device__ __forceinline__ void mbar_wait(uint32_t a, uint32_t phase) {
    asm volatile(
        "{\n\t.reg .pred P;\n\t"
        "WL%=:\n\t"
        "mbarrier.try_wait.parity.acquire.cta.shared::cta.b64 P,[%0],%1,0x989680;\n\t"
        "@P bra WD%=;\n\t"
        "bra WL%=;\n\t"
        "WD%=:\n\t}"
        ::"r"(a), "r"(phase) : "memory");
}
__device__ __forceinline__ void bulkcp(uint32_t dsh, const void* g, uint32_t n, uint32_t mb) {
    asm volatile("cp.async.bulk.shared::cta.global.mbarrier::complete_tx::bytes [%0],[%1],%2,[%3];"
                 ::"r"(dsh), "l"(g), "r"(n), "r"(mb) : "memory");
}

__device__ __forceinline__ void fill8(const float* __restrict__ Xh, const int* __restrict__ smk,
                                      uint32_t dsh, uint32_t mb, int t, int lane) {
    int ntok = (t == 62) ? 4 : 8;
    int tok = t * 8 + lane;
    bool act = (lane < ntok) && (smk[tok] == 0);
    unsigned bal = __ballot_sync(0xffffffffu, act);
    int cnt = __popc(bal);
    if (cnt == 0) {
        if (lane == 0) {
            mbar_expect(mb, 2048);
            bulkcp(dsh, Xh + (size_t)t * 8 * 512, 2048, mb);
        }
    } else {
        if (lane == 0) mbar_expect(mb, (uint32_t)cnt * 2048);
        __syncwarp();
        if (act) bulkcp(dsh + lane * 2048, Xh + (size_t)tok * 512, 2048, mb);
    }
}

// =============== kS: state = [x0,dc]@W_fc + pool@W_fc1 ; grid(4,32) x 256, unroll-8
__global__ void __launch_bounds__(256) kS(const float* __restrict__ X, const float* __restrict__ pool,
                                          const float* __restrict__ dc, const float* __restrict__ Wfc,
                                          const float* __restrict__ Wfc1) {
    __shared__ float sx[512 * 8], sp[512 * 8], sdc[8];
    int j0 = blockIdx.x * 128, b0 = blockIdx.y * 8, tid = threadIdx.x;
    for (int i = tid; i < 4096; i += 256) {
        int bb = i >> 9, e = i & 511;
        sx[e * 8 + bb] = X[(size_t)(b0 + bb) * (Nn * Dd) + e];
        sp[e * 8 + bb] = pool[(b0 + bb) * Dd + e];
    }
    if (tid < 8) sdc[tid] = dc[b0 + tid];
    __syncthreads();
    int jt = tid & 127, th = tid >> 7;
    int j = j0 + jt;
    unsigned long long acc[2] = {0ULL, 0ULL};
    for (int f8 = 0; f8 < 512; f8 += 8) {
        float w0v[8], w1v[8];
#pragma unroll
        for (int u = 0; u < 8; u++) { w0v[u] = Wfc[(f8 + u) * Dd + j]; w1v[u] = Wfc1[(f8 + u) * Dd + j]; }
#pragma unroll
        for (int u = 0; u < 8; u++) {
            int e = f8 + u;
            unsigned long long w00 = pack2(w0v[u], w0v[u]), w11 = pack2(w1v[u], w1v[u]);
            ulonglong2 a = *(const ulonglong2*)(sx + e * 8 + th * 4);
            ulonglong2 c = *(const ulonglong2*)(sp + e * 8 + th * 4);
            ffma2(acc[0], a.x, w00); ffma2(acc[0], c.x, w11);
            ffma2(acc[1], a.y, w00); ffma2(acc[1], c.y, w11);
        }
    }
    float wl = Wfc[512 * Dd + j];
#pragma unroll
    for (int p = 0; p < 2; p++) {
        float a, b;
        unpack2(acc[p], a, b);
        int bbase = b0 + th * 4 + 2 * p;
        g_state[bbase * Dd + j] = a + sdc[th * 4 + 2 * p] * wl;
        g_state[(bbase + 1) * Dd + j] = b + sdc[th * 4 + 2 * p + 1] * wl;
    }
}

// =============== kMM: Out = A@W ; grid(4,32) x 256, unroll-8
__global__ void __launch_bounds__(256) kMM(const float* __restrict__ W, int mode) {
    __shared__ float sa[512 * 8];
    const float* A = mode ? g_mhaH : g_state;
    float* Out = mode ? g_mo : g_Qf;
    int j0 = blockIdx.x * 128, b0 = blockIdx.y * 8, tid = threadIdx.x;
    for (int i = tid; i < 4096; i += 256) sa[(i & 511) * 8 + (i >> 9)] = A[(b0 + (i >> 9)) * Dd + (i & 511)];
    __syncthreads();
    int jt = tid & 127, th = tid >> 7;
    int j = j0 + jt;
    unsigned long long acc[2] = {0ULL, 0ULL};
    for (int f8 = 0; f8 < 512; f8 += 8) {
        float wv[8];
#pragma unroll
        for (int u = 0; u < 8; u++) wv[u] = W[(f8 + u) * Dd + j];
#pragma unroll
        for (int u = 0; u < 8; u++) {
            unsigned long long ww = pack2(wv[u], wv[u]);
            ulonglong2 a = *(const ulonglong2*)(sa + (f8 + u) * 8 + th * 4);
            ffma2(acc[0], a.x, ww); ffma2(acc[1], a.y, ww);
        }
    }
#pragma unroll
    for (int p = 0; p < 2; p++) {
        float a, b;
        unpack2(acc[p], a, b);
        int bbase = b0 + th * 4 + 2 * p;
        Out[bbase * Dd + j] = a;
        Out[(bbase + 1) * Dd + j] = b;
    }
}

// =============== kQt: Qt[b][h][e] ; grid(4,32) x 256 (head-split) — unchanged R15
__global__ void __launch_bounds__(256) kQt(const float* __restrict__ Wk) {
    __shared__ float sq[8 * 512];
    int e0 = blockIdx.x * 128, b0 = blockIdx.y * 8, tid = threadIdx.x;
    for (int i = tid; i < 4096; i += 256) sq[i] = g_Qf[(b0 + (i >> 9)) * Dd + (i & 511)];
    __syncthreads();
    int jt = tid & 127, th = tid >> 7;
    int e = e0 + jt;
    const float* wrow = Wk + (size_t)e * Dd;
    for (int h = th * 4; h < th * 4 + 4; h++) {
        unsigned long long accp[8];
#pragma unroll
        for (int k = 0; k < 8; k++) accp[k] = 0ULL;
        const float* wr = wrow + h * 64;
#pragma unroll
        for (int d4 = 0; d4 < 16; d4++) {
            float4 wv = *(const float4*)(wr + d4 * 4);
            unsigned long long w01 = pack2(wv.x, wv.y), w23 = pack2(wv.z, wv.w);
#pragma unroll
            for (int bb = 0; bb < 8; bb++) {
                ulonglong2 q2 = *(const ulonglong2*)(sq + bb * 512 + h * 64 + d4 * 4);
                ffma2(accp[bb], w01, q2.x);
                ffma2(accp[bb], w23, q2.y);
            }
        }
#pragma unroll
        for (int bb = 0; bb < 8; bb++) {
            float a, b;
            unpack2(accp[bb], a, b);
            g_Qt[(size_t)(b0 + bb) * 4096 + h * 512 + e] = (a + b) * NORM_MHA;
        }
    }
}

// =============== kB: pass 1, half-batch CTAs (grid (2,256) x 256) — R11 proven version
#define KB_SMEM_FLOATS 13086
__global__ void __launch_bounds__(256, 4) kB(const float* __restrict__ X, const int* __restrict__ mask) {
    extern __shared__ float sm[];
    float* xs = sm;
    float* cpart = sm + 12288;
    float* pbuf = sm + 12416;
    float* s_m = sm + 12544;
    float* s_l = sm + 12552;
    float* s_scale = sm + 12560;
    float* s_any = sm + 12576;
    int* smk = (int*)(sm + 12580);
    uint32_t mb0 = smem_u32(sm + 13080);

    int half = blockIdx.x, b = blockIdx.y;
    int tid = threadIdx.x, w = tid >> 5, lane = tid & 31;
    const float* Xh = X + (size_t)b * (Nn * Dd) + (size_t)half * 500 * Dd;
    const int* mbp = mask + b * Nn + half * 500;
    for (int i = tid; i < 500; i += 256) smk[i] = mbp[i];
    if (tid < 8) { s_m[tid] = NEGINF; s_l[tid] = 0.f; }
    if (tid < 3) mbar_init(mb0 + tid * 8, 1);

    int tg = w >> 2, qh = (w >> 1) & 1, eh = w & 1;
    int e_lo = eh * 256 + (lane << 2);
    unsigned long long qt2[2][8];
    {
        const float* Qtb = g_Qt + (size_t)b * 4096;
        float qv[4][8];
#pragma unroll
        for (int hh = 0; hh < 4; hh++) {
            int h = qh * 4 + hh;
            float4 a = *(const float4*)(Qtb + h * 512 + e_lo);
            float4 c = *(const float4*)(Qtb + h * 512 + e_lo + 128);
            qv[hh][0] = a.x; qv[hh][1] = a.y; qv[hh][2] = a.z; qv[hh][3] = a.w;
            qv[hh][4] = c.x; qv[hh][5] = c.y; qv[hh][6] = c.z; qv[hh][7] = c.w;
        }
#pragma unroll
        for (int e = 0; e < 8; e++) {
            qt2[0][e] = pack2(qv[0][e], qv[1][e]);
            qt2[1][e] = pack2(qv[2][e], qv[3][e]);
        }
    }
    unsigned long long ys64[8];
#pragma unroll
    for (int h = 0; h < 8; h++) ys64[h] = 0ULL;

    __syncthreads();
    uint32_t xs_sh = smem_u32(xs);
    if (w == 0) fill8(Xh, smk, xs_sh, mb0, 0, lane);

    for (int t = 0; t < 63; t++) {
        int t0 = t * 8;
        int ntok = (t == 62) ? 4 : 8;
        int s = t % 3, par = t & 1;
        if (w == 0 && t < 62) {
            int ns = (t + 1) % 3;
            fill8(Xh, smk, xs_sh + ns * 16384, mb0 + ns * 8, t + 1, lane);
        }
        mbar_wait(mb0 + s * 8, (t / 3) & 1);
        if (tid == 0) s_any[par] = 0.f;
        const float* xc = xs + s * 4096;
#pragma unroll
        for (int k = 0; k < 4; k++) {
            int n = tg * 4 + k;
            if (n >= ntok || smk[t0 + n]) continue;
            const float* row = xc + (n << 9);
            float4 xa = *(const float4*)(row + e_lo);
            float4 xb2 = *(const float4*)(row + e_lo + 128);
            unsigned long long av0 = 0, av1 = 0, xx;
            xx = pack2(xa.x, xa.x); ffma2(av0, xx, qt2[0][0]); ffma2(av1, xx, qt2[1][0]);
            xx = pack2(xa.y, xa.y); ffma2(av0, xx, qt2[0][1]); ffma2(av1, xx, qt2[1][1]);
            xx = pack2(xa.z, xa.z); ffma2(av0, xx, qt2[0][2]); ffma2(av1, xx, qt2[1][2]);
            xx = pack2(xa.w, xa.w); ffma2(av0, xx, qt2[0][3]); ffma2(av1, xx, qt2[1][3]);
            xx = pack2(xb2.x, xb2.x); ffma2(av0, xx, qt2[0][4]); ffma2(av1, xx, qt2[1][4]);
            xx = pack2(xb2.y, xb2.y); ffma2(av0, xx, qt2[0][5]); ffma2(av1, xx, qt2[1][5]);
            xx = pack2(xb2.z, xb2.z); ffma2(av0, xx, qt2[0][6]); ffma2(av1, xx, qt2[1][6]);
            xx = pack2(xb2.w, xb2.w); ffma2(av0, xx, qt2[0][7]); ffma2(av1, xx, qt2[1][7]);
            float a0, a1, a2, a3;
            unpack2(av0, a0, a1); unpack2(av1, a2, a3);
#pragma unroll
            for (int off = 16; off > 0; off >>= 1) {
                a0 += __shfl_xor_sync(0xffffffffu, a0, off);
                a1 += __shfl_xor_sync(0xffffffffu, a1, off);
                a2 += __shfl_xor_sync(0xffffffffu, a2, off);
                a3 += __shfl_xor_sync(0xffffffffu, a3, off);
            }
            if (lane == 0)
                *(float4*)(cpart + (eh * 8 + n) * 8 + qh * 4) = make_float4(a0, a1, a2, a3);
        }
        __syncthreads();
        {
            int h = w;
            float u = NEGINF;
            if (lane < ntok && smk[t0 + lane] == 0) u = cpart[lane * 8 + h] + cpart[64 + lane * 8 + h];
            float tmax = u;
#pragma unroll
            for (int off = 16; off > 0; off >>= 1) tmax = fmaxf(tmax, __shfl_xor_sync(0xffffffffu, tmax, off));
            float m_old = s_m[h], m_new = fmaxf(m_old, tmax);
            float p = (u != NEGINF) ? __expf(u - m_new) : 0.f;
            if (lane < 8) pbuf[par * 64 + lane * 8 + h] = p;
            float ps = p;
#pragma unroll
            for (int off = 16; off > 0; off >>= 1) ps += __shfl_xor_sync(0xffffffffu, ps, off);
            if (lane == 0) {
                float sc = 1.f;
                if (m_new > m_old) { sc = (m_old == NEGINF) ? 1.f : __expf(m_old - m_new); s_m[h] = m_new; }
                s_scale[par * 8 + h] = sc;
                s_l[h] = s_l[h] * sc + ps;
                if (sc != 1.f) s_any[par] = 1.f;
            }
        }
        __syncthreads();
        if (s_any[par] != 0.f) {
#pragma unroll
            for (int h = 0; h < 8; h++) {
                float s2 = s_scale[par * 8 + h];
                fmul2(ys64[h], pack2(s2, s2));
            }
        }
        const float* pb = pbuf + par * 64;
        for (int k = 0; k < ntok; k++) {
            if (smk[t0 + k]) continue;
            unsigned long long xv = *(const unsigned long long*)(xc + (k << 9) + (tid << 1));
            float4 p0 = *(const float4*)(pb + (k << 3));
            float4 p1 = *(const float4*)(pb + (k << 3) + 4);
            ffma2(ys64[0], xv, pack2(p0.x, p0.x));
            ffma2(ys64[1], xv, pack2(p0.y, p0.y));
            ffma2(ys64[2], xv, pack2(p0.z, p0.z));
            ffma2(ys64[3], xv, pack2(p0.w, p0.w));
            ffma2(ys64[4], xv, pack2(p1.x, p1.x));
            ffma2(ys64[5], xv, pack2(p1.y, p1.y));
            ffma2(ys64[6], xv, pack2(p1.z, p1.z));
            ffma2(ys64[7], xv, pack2(p1.w, p1.w));
        }
    }
    __syncthreads();
    float* yo = g_ys2 + ((size_t)(half * Bb + b)) * 4096;
#pragma unroll
    for (int h = 0; h < 8; h++) {
        float a, bv;
        unpack2(ys64[h], a, bv);
        *(float2*)(yo + h * 512 + (tid << 1)) = make_float2(a, bv);
    }
    if (tid < 8) {
        g_m2[(half * Bb + b) * 8 + tid] = s_m[tid];
        g_l2[(half * Bb + b) * 8 + tid] = s_l[tid];
    }
}

// =============== kV: merge halves + mhaH = (ysum/l)@Wv ; grid(4,32) x 256, unroll-8
__global__ void __launch_bounds__(256) kV(const float* __restrict__ Wv) {
    __shared__ float syc[2 * 4096];
    __shared__ float s0a[16], s1a[16];
    int h0 = blockIdx.x * 2, b0 = blockIdx.y * 8, tid = threadIdx.x;
    if (tid < 16) {
        int bb = tid >> 1, hl = tid & 1;
        int b = b0 + bb, h = h0 + hl;
        float m0 = g_m2[b * 8 + h], m1 = g_m2[(Bb + b) * 8 + h];
        float l0 = g_l2[b * 8 + h], l1 = g_l2[(Bb + b) * 8 + h];
        float M = fmaxf(m0, m1);
        float e0 = __expf(m0 - M), e1 = __expf(m1 - M);
        float L = l0 * e0 + l1 * e1;
        s0a[tid] = e0 / L;
        s1a[tid] = e1 / L;
    }
    __syncthreads();
    for (int i = tid; i < 8192; i += 256) {
        int hl = i >> 12, bb = (i >> 9) & 7, e = i & 511;
        int b = b0 + bb, h = h0 + hl;
        float v = g_ys2[(size_t)b * 4096 + h * 512 + e] * s0a[bb * 2 + hl]
                + g_ys2[(size_t)(Bb + b) * 4096 + h * 512 + e] * s1a[bb * 2 + hl];
        syc[hl * 4096 + e * 8 + bb] = v;
    }
    __syncthreads();
    int jt = tid & 127, th = tid >> 7;
    int j = blockIdx.x * 128 + jt, hl = jt >> 6;
    const float* base = syc + hl * 4096;
    unsigned long long acc[2] = {0ULL, 0ULL};
    for (int f8 = 0; f8 < 512; f8 += 8) {
        float wv[8];
#pragma unroll
        for (int u = 0; u < 8; u++) wv[u] = Wv[(f8 + u) * Dd + j];
#pragma unroll
        for (int u = 0; u < 8; u++) {
            unsigned long long ww = pack2(wv[u], wv[u]);
            ulonglong2 y = *(const ulonglong2*)(base + (f8 + u) * 8 + th * 4);
            ffma2(acc[0], y.x, ww); ffma2(acc[1], y.y, ww);
        }
    }
#pragma unroll
    for (int p = 0; p < 2; p++) {
        float a, b;
        unpack2(acc[p], a, b);
        int bbase = b0 + th * 4 + 2 * p;
        g_mhaH[bbase * Dd + j] = a;
        g_mhaH[(bbase + 1) * Dd + j] = b;
    }
}

// =============== kZ: z = norm_ptr * Wkp@mo ; grid(4,32) x 256, unroll-8
__global__ void __launch_bounds__(256) kZ(const float* __restrict__ Wkp) {
    __shared__ float smo[512 * 8];
    int e0 = blockIdx.x * 128, b0 = blockIdx.y * 8, tid = threadIdx.x;
    for (int i = tid; i < 4096; i += 256) smo[(i & 511) * 8 + (i >> 9)] = g_mo[(b0 + (i >> 9)) * Dd + (i & 511)];
    __syncthreads();
    int jt = tid & 127, th = tid >> 7;
    int e = e0 + jt;
    const float* wrow = Wkp + (size_t)e * Dd;
    unsigned long long acc[2] = {0ULL, 0ULL};
    for (int f8 = 0; f8 < 512; f8 += 8) {
        float4 wa = *(const float4*)(wrow + f8);
        float4 wb = *(const float4*)(wrow + f8 + 4);
        float wv[8] = {wa.x, wa.y, wa.z, wa.w, wb.x, wb.y, wb.z, wb.w};
#pragma unroll
        for (int u = 0; u < 8; u++) {
            unsigned long long ww = pack2(wv[u], wv[u]);
            ulonglong2 m = *(const ulonglong2*)(smo + (f8 + u) * 8 + th * 4);
            ffma2(acc[0], m.x, ww); ffma2(acc[1], m.y, ww);
        }
    }
#pragma unroll
    for (int p = 0; p < 2; p++) {
        float a, b;
        unpack2(acc[p], a, b);
        int bbase = b0 + th * 4 + 2 * p;
        g_z[bbase * Dd + e] = a * NORM_PTR;
        g_z[(bbase + 1) * Dd + e] = b * NORM_PTR;
    }
}

// =============== kD1: tv = tanh(x.z)*10 ; grid(4,256) x 256 ; 8 loads in flight
__global__ void __launch_bounds__(256) kD1(const float* __restrict__ X, const int* __restrict__ mask) {
    __shared__ int smk[250];
    int q = blockIdx.x, b = blockIdx.y;
    int tid = threadIdx.x, w = tid >> 5, lane = tid & 31;
    const int* mbp = mask + b * Nn + q * 250;
    for (int i = tid; i < 250; i += 256) smk[i] = mbp[i];
    const float* zb = g_z + b * Dd;
    float4 z[4];
#pragma unroll
    for (int c = 0; c < 4; c++) z[c] = *(const float4*)(zb + c * 128 + lane * 4);
    const float* Xq = X + (size_t)b * (Nn * Dd) + (size_t)q * 250 * Dd;
    float* tvq = g_tv + b * Nn + q * 250;
    __syncthreads();
    for (int g = w; g < 63; g += 8) {
        int n0 = g * 4;
        int nr = (g == 62) ? 2 : 4;
        int m[4];
        float acc[4] = {0.f, 0.f, 0.f, 0.f};
#pragma unroll
        for (int r = 0; r < 4; r++) m[r] = (r < nr) ? smk[n0 + r] : 1;
#pragma unroll
        for (int cc = 0; cc < 2; cc++) {   // 2 super-chunks of 2: 8 loads batched
            float4 xr[4][2];
#pragma unroll
            for (int c2 = 0; c2 < 2; c2++)
#pragma unroll
                for (int r = 0; r < 4; r++)
                    if (!m[r]) xr[r][c2] = *(const float4*)(Xq + (size_t)(n0 + r) * Dd + (cc * 2 + c2) * 128 + lane * 4);
#pragma unroll
            for (int c2 = 0; c2 < 2; c2++) {
                int c = cc * 2 + c2;
#pragma unroll
                for (int r = 0; r < 4; r++)
                    if (!m[r])
                        acc[r] += xr[r][c2].x * z[c].x + xr[r][c2].y * z[c].y + xr[r][c2].z * z[c].z + xr[r][c2].w * z[c].w;
            }
        }
#pragma unroll
        for (int off = 16; off > 0; off >>= 1) {
#pragma unroll
            for (int r = 0; r < 4; r++) acc[r] += __shfl_xor_sync(0xffffffffu, acc[r], off);
        }
        if (lane == 0) {
#pragma unroll
            for (int r = 0; r < 4; r++)
                if (r < nr) tvq[n0 + r] = m[r] ? NEGINF : tanhf(acc[r]) * 10.f;
        }
    }
}

// =============== kD2: masked softmax over tv ; grid 256 x 512
__global__ void __launch_bounds__(512) kD2(float* __restrict__ out) {
    __shared__ float tvals[Nn];
    __shared__ float red[16];
    __shared__ float bcv;
    int b = blockIdx.x, tid = threadIdx.x, w = tid >> 5, lane = tid & 31;
    const float* tvg = g_tv + b * Nn;
    for (int i = tid; i < Nn; i += 512) tvals[i] = tvg[i];
    __syncthreads();
    float t0v = tvals[tid];
    int n1 = tid + 512;
    float t1v = (n1 < Nn) ? tvals[n1] : NEGINF;
    float wmax = fmaxf(t0v, t1v);
#pragma unroll
    for (int off = 16; off > 0; off >>= 1) wmax = fmaxf(wmax, __shfl_xor_sync(0xffffffffu, wmax, off));
    if (lane == 0) red[w] = wmax;
    __syncthreads();
    if (tid == 0) {
        float m = red[0];
#pragma unroll
        for (int i = 1; i < 16; i++) m = fmaxf(m, red[i]);
        bcv = m;
    }
    __syncthreads();
    float gmax = bcv;
    float ev0 = (t0v == NEGINF) ? 0.f : __expf(t0v - gmax);
    float ev1 = (t1v == NEGINF) ? 0.f : __expf(t1v - gmax);
    float ps = ev0 + ev1;
#pragma unroll
    for (int off = 16; off > 0; off >>= 1) ps += __shfl_xor_sync(0xffffffffu, ps, off);
    __syncthreads();
    if (lane == 0) red[w] = ps;
    __syncthreads();
    if (tid == 0) {
        float s = 0.f;
#pragma unroll
        for (int i = 0; i < 16; i++) s += red[i];
        bcv = 1.f / s;
    }
    __syncthreads();
    float inv = bcv;
    out[b * Nn + tid] = ev0 * inv;
    if (n1 < Nn) out[b * Nn + n1] = ev1 * inv;
}

extern "C" void kernel_launch(void* const* d_in, const int* in_sizes, int n_in,
                              void* d_out, int out_size) {
    const float* X    = (const float*)d_in[0];
    const float* pool = (const float*)d_in[1];
    const float* dc   = (const float*)d_in[2];
    const int*   mask = (const int*)d_in[3];
    const float* Wfc  = (const float*)d_in[4];
    const float* Wfc1 = (const float*)d_in[5];
    const float* Wq   = (const float*)d_in[6];
    const float* Wkm  = (const float*)d_in[7];
    const float* Wv   = (const float*)d_in[8];
    const float* Wo   = (const float*)d_in[9];
    const float* Wkp  = (const float*)d_in[10];
    float* out = (float*)d_out;
    const int KB_SMEM = KB_SMEM_FLOATS * 4;
    cudaFuncSetAttribute(kB, cudaFuncAttributeMaxDynamicSharedMemorySize, KB_SMEM);
    kS<<<dim3(4, 32), 256>>>(X, pool, dc, Wfc, Wfc1);
    kMM<<<dim3(4, 32), 256>>>(Wq, 0);
    kQt<<<dim3(4, 32), 256>>>(Wkm);
    kB<<<dim3(2, 256), 256, KB_SMEM>>>(X, mask);
    kV<<<dim3(4, 32), 256>>>(Wv);
    kMM<<<dim3(4, 32), 256>>>(Wo, 1);
    kZ<<<dim3(4, 32), 256>>>(Wkp);
    kD1<<<dim3(4, 256), 256>>>(X, mask);
    kD2<<<256, 512>>>(out);
}